// round 2
// baseline (speedup 1.0000x reference)
#include <cuda_runtime.h>
#include <cuda_bf16.h>

// ApproxEMD: B=16, N=2048, D=3.
// Never materialize the 2048x2048 matrices. Per auction step:
//   Pass A (columns): S_E[m] = sum_n E, S_EC[m] = sum_n E*c[n],  E = exp(ef*d(n,m))
//   small1:  s1 = cost*S_E; s2 = cost*S_EC/(s1+EPS); wt = min(cost/(s2+EPS),1);
//            g = cost*wt/(s1+EPS); cost = max(cost - s2*wt, 0)
//   Pass B (rows):    R[n] = sum_m E*g[m];  out += c[n]*sum_m E*g[m]*d(n,m)
//   small2:  curr = max(curr - curr*R, 0)
// d(n,m) = |p_n|^2 + |l_m|^2 - 2 p.l recomputed on the fly (points cached in smem).

#define BB 16
#define NN 2048
#define BN (BB*NN)
#define EPSV 1e-9f

__device__ float g_cost[BN];
__device__ float g_curr[BN];
__device__ float g_SE[BN];
__device__ float g_SEC[BN];
__device__ float g_g[BN];
__device__ float g_R[BN];
__device__ float g_pn[BN];   // |p_n|^2
__device__ float g_lm[BN];   // |l_m|^2
__device__ double g_out;

__device__ __forceinline__ float ex2f(float x) {
    float r;
    asm("ex2.approx.f32 %0, %1;" : "=f"(r) : "f"(x));
    return r;
}

__global__ void k_init(const float* __restrict__ preds,
                       const float* __restrict__ labels) {
    int idx = blockIdx.x * 256 + threadIdx.x;
    if (idx >= BN) return;
    const float* p = preds + (size_t)idx * 3;
    const float* l = labels + (size_t)idx * 3;
    float px = p[0], py = p[1], pz = p[2];
    float lx = l[0], ly = l[1], lz = l[2];
    g_pn[idx] = px * px + py * py + pz * pz;
    g_lm[idx] = lx * lx + ly * ly + lz * lz;
    g_cost[idx] = 1.0f;
    g_curr[idx] = 1.0f;
    g_SE[idx] = 0.0f;
    g_SEC[idx] = 0.0f;
    g_R[idx] = 0.0f;
    if (idx == 0) g_out = 0.0;
}

// Pass A: column sums. grid (nChunks=4, colBlocks=8, B=16), block 256.
// thread -> one column m; iterates a 512-row chunk of n.
__global__ void k_colpass(const float* __restrict__ preds,
                          const float* __restrict__ labels, float ef) {
    const int b = blockIdx.z;
    const int m = blockIdx.y * 256 + threadIdx.x;
    const int nBase = blockIdx.x * 512;
    __shared__ float4 sp[512];   // (px,py,pz, efl*|p|^2)
    __shared__ float sc[512];    // currency

    const float l2e = 1.4426950408889634f;
    const float efl = ef * l2e;

    for (int i = threadIdx.x; i < 512; i += 256) {
        int n = nBase + i;
        const float* p = preds + ((size_t)b * NN + n) * 3;
        sp[i] = make_float4(p[0], p[1], p[2], efl * g_pn[b * NN + n]);
        sc[i] = g_curr[b * NN + n];
    }
    __syncthreads();

    const float* l = labels + ((size_t)b * NN + m) * 3;
    const float lx = l[0], ly = l[1], lz = l[2];
    const float Bm = efl * g_lm[b * NN + m];
    const float c2 = -2.0f * efl;

    float sE = 0.0f, sEC = 0.0f;
#pragma unroll 8
    for (int i = 0; i < 512; i++) {
        float4 P = sp[i];
        float dot = fmaf(P.z, lz, fmaf(P.y, ly, P.x * lx));
        float xx = fmaf(dot, c2, P.w + Bm);     // = ef*log2e*d
        float E = ex2f(xx);
        sE += E;
        sEC = fmaf(E, sc[i], sEC);
    }
    atomicAdd(&g_SE[b * NN + m], sE);
    atomicAdd(&g_SEC[b * NN + m], sEC);
}

// per-(b,m) scalar update: compute g, update cost, zero sums for next step.
__global__ void k_small1() {
    int idx = blockIdx.x * 256 + threadIdx.x;
    if (idx >= BN) return;
    float se = g_SE[idx], sec = g_SEC[idx], cost = g_cost[idx];
    float s1 = cost * se;
    float s2 = cost * sec / (s1 + EPSV);
    float wt = fminf(cost / (s2 + EPSV), 1.0f);
    g_g[idx] = cost * wt / (s1 + EPSV);
    g_cost[idx] = fmaxf(cost - s2 * wt, 0.0f);
    g_SE[idx] = 0.0f;
    g_SEC[idx] = 0.0f;
}

// Pass B: row sums + output accumulation. grid (mChunks=4, rowBlocks=8, B=16).
// thread -> one row n; iterates a 512-col chunk of m.
__global__ void k_rowpass(const float* __restrict__ preds,
                          const float* __restrict__ labels, float ef) {
    const int b = blockIdx.z;
    const int n = blockIdx.y * 256 + threadIdx.x;
    const int mBase = blockIdx.x * 512;
    __shared__ float4 sl[512];   // (lx,ly,lz, |l|^2)
    __shared__ float sg[512];    // g[m]
    __shared__ float sred[8];

    for (int i = threadIdx.x; i < 512; i += 256) {
        int m = mBase + i;
        const float* l = labels + ((size_t)b * NN + m) * 3;
        sl[i] = make_float4(l[0], l[1], l[2], g_lm[b * NN + m]);
        sg[i] = g_g[b * NN + m];
    }
    __syncthreads();

    const float* p = preds + ((size_t)b * NN + n) * 3;
    const float px = p[0], py = p[1], pz = p[2];
    const float pn = g_pn[b * NN + n];
    const float c = g_curr[b * NN + n];
    const float l2e = 1.4426950408889634f;
    const float efl = ef * l2e;

    float accR = 0.0f, accO = 0.0f;
#pragma unroll 8
    for (int i = 0; i < 512; i++) {
        float4 L = sl[i];
        float dot = fmaf(L.z, pz, fmaf(L.y, py, L.x * px));
        float dv = fmaf(dot, -2.0f, pn + L.w);  // pairwise distance
        float E = ex2f(dv * efl);
        float t = E * sg[i];
        accR += t;
        accO = fmaf(t, dv, accO);
    }
    atomicAdd(&g_R[b * NN + n], accR);

    // block-reduce c * accO -> single double atomic per block
    float v = c * accO;
#pragma unroll
    for (int off = 16; off > 0; off >>= 1)
        v += __shfl_down_sync(0xFFFFFFFFu, v, off);
    if ((threadIdx.x & 31) == 0) sred[threadIdx.x >> 5] = v;
    __syncthreads();
    if (threadIdx.x == 0) {
        float s = 0.0f;
#pragma unroll
        for (int w = 0; w < 8; w++) s += sred[w];
        atomicAdd(&g_out, (double)s);
    }
}

// per-(b,n) currency update, zero R for next step.
__global__ void k_small2() {
    int idx = blockIdx.x * 256 + threadIdx.x;
    if (idx >= BN) return;
    float c = g_curr[idx];
    float r = g_R[idx];
    g_curr[idx] = fmaxf(c - c * r, 0.0f);
    g_R[idx] = 0.0f;
}

__global__ void k_write(float* out) {
    out[0] = (float)g_out;
}

extern "C" void kernel_launch(void* const* d_in, const int* in_sizes, int n_in,
                              void* d_out, int out_size) {
    const float* preds = (const float*)d_in[0];
    const float* labels = (const float*)d_in[1];
    float* out = (float*)d_out;

    static const float EF[10] = {
        -16384.0f, -4096.0f, -1024.0f, -256.0f, -64.0f,
        -16.0f, -4.0f, -1.0f, -0.25f, 0.0f
    };

    k_init<<<BN / 256, 256>>>(preds, labels);

    dim3 gridA(4, 8, BB);   // nChunks x colBlocks x batch
    dim3 gridB(4, 8, BB);   // mChunks x rowBlocks x batch
    for (int s = 0; s < 10; s++) {
        float ef = EF[s];
        k_colpass<<<gridA, 256>>>(preds, labels, ef);
        k_small1<<<BN / 256, 256>>>();
        k_rowpass<<<gridB, 256>>>(preds, labels, ef);
        k_small2<<<BN / 256, 256>>>();
    }
    k_write<<<1, 1>>>(out);
}

// round 3
// speedup vs baseline: 1.2632x; 1.2632x over previous
#include <cuda_runtime.h>
#include <cuda_bf16.h>

// ApproxEMD: B=16, N=2048, D=3. Flash-style: never materialize NxN matrices.
// Per auction step (ef != 0):
//   colpass: S_E[m] = sum_n E, S_EC[m] = sum_n E*c[n], E = exp(ef*d(n,m))
//   small1:  s1=cost*S_E; s2=cost*S_EC/(s1+eps); wt=min(cost/(s2+eps),1);
//            g=cost*wt/(s1+eps); cost=max(cost-s2*wt,0)
//   rowpass: R[n] = sum_m E*g[m]; out += c[n]*sum_m E*g[m]*d(n,m)
//   small2:  curr = max(curr - curr*R, 0)
// Last step (ef==0): E==1 -> closed form O(N).
// Inner loops use packed f32x2 FMA (Blackwell FFMA2) + MUFU.EX2.

#define BB 16
#define NN 2048
#define BN (BB*NN)
#define EPSV 1e-9f
#define CH 128
#define NCHUNK (NN/CH)   // 16

__device__ float g_cost[BN];
__device__ float g_curr[BN];
__device__ float g_g[BN];
__device__ float g_pn[BN];   // |p_n|^2
__device__ float g_lm[BN];   // |l_m|^2
__device__ float g_SEp[NCHUNK][BN];
__device__ float g_SECp[NCHUNK][BN];
__device__ float g_Rp[NCHUNK][BN];
__device__ double g_out;

typedef unsigned long long u64;

__device__ __forceinline__ float ex2f(float x) {
    float r;
    asm("ex2.approx.f32 %0, %1;" : "=f"(r) : "f"(x));
    return r;
}
__device__ __forceinline__ u64 pk(float lo, float hi) {
    u64 d;
    asm("mov.b64 %0, {%1, %2};" : "=l"(d)
        : "r"(__float_as_uint(lo)), "r"(__float_as_uint(hi)));
    return d;
}
__device__ __forceinline__ void upk(u64 v, float& lo, float& hi) {
    unsigned a, b;
    asm("mov.b64 {%0, %1}, %2;" : "=r"(a), "=r"(b) : "l"(v));
    lo = __uint_as_float(a); hi = __uint_as_float(b);
}
__device__ __forceinline__ u64 fma2(u64 a, u64 b, u64 c) {
    u64 d;
    asm("fma.rn.f32x2 %0, %1, %2, %3;" : "=l"(d) : "l"(a), "l"(b), "l"(c));
    return d;
}
__device__ __forceinline__ u64 add2(u64 a, u64 b) {
    u64 d;
    asm("add.rn.f32x2 %0, %1, %2;" : "=l"(d) : "l"(a), "l"(b));
    return d;
}
__device__ __forceinline__ u64 mul2(u64 a, u64 b) {
    u64 d;
    asm("mul.rn.f32x2 %0, %1, %2;" : "=l"(d) : "l"(a), "l"(b));
    return d;
}

__global__ void k_init(const float* __restrict__ preds,
                       const float* __restrict__ labels) {
    int idx = blockIdx.x * 256 + threadIdx.x;
    if (idx >= BN) return;
    const float* p = preds + (size_t)idx * 3;
    const float* l = labels + (size_t)idx * 3;
    g_pn[idx] = p[0]*p[0] + p[1]*p[1] + p[2]*p[2];
    g_lm[idx] = l[0]*l[0] + l[1]*l[1] + l[2]*l[2];
    g_cost[idx] = 1.0f;
    g_curr[idx] = 1.0f;
    if (idx == 0) g_out = 0.0;
}

// colpass: thread owns 4 columns m (2 packed pairs); smem chunk of rows n.
// grid (NCHUNK, 2, BB), block 256.
__global__ void __launch_bounds__(256) k_colpass(
    const float* __restrict__ preds, const float* __restrict__ labels,
    float efl /* ef*log2e */) {
    const int b = blockIdx.z;
    const int chunk = blockIdx.x;
    const int m0 = blockIdx.y * 1024 + threadIdx.x;
    __shared__ float4 sp[CH];   // (px,py,pz, efl*|p|^2)
    __shared__ float  sc[CH];   // currency

    for (int i = threadIdx.x; i < CH; i += 256) {
        int n = chunk * CH + i;
        const float* p = preds + ((size_t)b * NN + n) * 3;
        sp[i] = make_float4(p[0], p[1], p[2], efl * g_pn[b * NN + n]);
        sc[i] = g_curr[b * NN + n];
    }
    __syncthreads();

    // column data: pairs A=(m0,m0+256), B=(m0+512,m0+768)
    const float* lA0 = labels + ((size_t)b * NN + m0) * 3;
    const float* lA1 = labels + ((size_t)b * NN + m0 + 256) * 3;
    const float* lB0 = labels + ((size_t)b * NN + m0 + 512) * 3;
    const float* lB1 = labels + ((size_t)b * NN + m0 + 768) * 3;
    u64 lxA = pk(lA0[0], lA1[0]), lyA = pk(lA0[1], lA1[1]), lzA = pk(lA0[2], lA1[2]);
    u64 lxB = pk(lB0[0], lB1[0]), lyB = pk(lB0[1], lB1[1]), lzB = pk(lB0[2], lB1[2]);
    u64 wbA = pk(efl * g_lm[b*NN+m0],     efl * g_lm[b*NN+m0+256]);
    u64 wbB = pk(efl * g_lm[b*NN+m0+512], efl * g_lm[b*NN+m0+768]);
    const float c2 = -2.0f * efl;
    const u64 c2d = pk(c2, c2);

    u64 sEA = 0ull, sECA = 0ull, sEB = 0ull, sECB = 0ull;
#pragma unroll 4
    for (int i = 0; i < CH; i++) {
        float4 P = sp[i];
        float cc = sc[i];
        u64 xd = pk(P.x, P.x), yd = pk(P.y, P.y), zd = pk(P.z, P.z);
        u64 wnd = pk(P.w, P.w), cd = pk(cc, cc);
        // pair A
        {
            u64 dot = fma2(zd, lzA, fma2(yd, lyA, mul2(xd, lxA)));
            u64 arg = fma2(dot, c2d, add2(wnd, wbA));   // = efl*d  (<= ~0)
            float a0, a1; upk(arg, a0, a1);
            u64 e = pk(ex2f(a0), ex2f(a1));
            sEA = add2(sEA, e);
            sECA = fma2(e, cd, sECA);
        }
        // pair B
        {
            u64 dot = fma2(zd, lzB, fma2(yd, lyB, mul2(xd, lxB)));
            u64 arg = fma2(dot, c2d, add2(wnd, wbB));
            float a0, a1; upk(arg, a0, a1);
            u64 e = pk(ex2f(a0), ex2f(a1));
            sEB = add2(sEB, e);
            sECB = fma2(e, cd, sECB);
        }
    }
    float se0, se1, se2, se3, sc0, sc1, sc2, sc3;
    upk(sEA, se0, se1); upk(sEB, se2, se3);
    upk(sECA, sc0, sc1); upk(sECB, sc2, sc3);
    g_SEp [chunk][b*NN+m0      ] = se0;
    g_SEp [chunk][b*NN+m0 + 256] = se1;
    g_SEp [chunk][b*NN+m0 + 512] = se2;
    g_SEp [chunk][b*NN+m0 + 768] = se3;
    g_SECp[chunk][b*NN+m0      ] = sc0;
    g_SECp[chunk][b*NN+m0 + 256] = sc1;
    g_SECp[chunk][b*NN+m0 + 512] = sc2;
    g_SECp[chunk][b*NN+m0 + 768] = sc3;
}

__global__ void k_small1() {
    int idx = blockIdx.x * 256 + threadIdx.x;
    if (idx >= BN) return;
    float se = 0.0f, sec = 0.0f;
#pragma unroll
    for (int ch = 0; ch < NCHUNK; ch++) {
        se += g_SEp[ch][idx];
        sec += g_SECp[ch][idx];
    }
    float cost = g_cost[idx];
    float s1 = cost * se;
    float s2 = cost * sec / (s1 + EPSV);
    float wt = fminf(cost / (s2 + EPSV), 1.0f);
    g_g[idx] = cost * wt / (s1 + EPSV);
    g_cost[idx] = fmaxf(cost - s2 * wt, 0.0f);
}

// rowpass: thread owns 4 rows n (2 packed pairs); smem chunk of columns m.
// grid (NCHUNK, 2, BB), block 256.
__global__ void __launch_bounds__(256) k_rowpass(
    const float* __restrict__ preds, const float* __restrict__ labels,
    float efl, float inv_efl) {
    const int b = blockIdx.z;
    const int chunk = blockIdx.x;
    const int n0 = blockIdx.y * 1024 + threadIdx.x;
    __shared__ float4 sl[CH];   // (lx,ly,lz, efl*|l|^2)
    __shared__ float  sg[CH];   // g[m]
    __shared__ float  sred[8];

    for (int i = threadIdx.x; i < CH; i += 256) {
        int m = chunk * CH + i;
        const float* l = labels + ((size_t)b * NN + m) * 3;
        sl[i] = make_float4(l[0], l[1], l[2], efl * g_lm[b * NN + m]);
        sg[i] = g_g[b * NN + m];
    }
    __syncthreads();

    const float* pA0 = preds + ((size_t)b * NN + n0) * 3;
    const float* pA1 = preds + ((size_t)b * NN + n0 + 256) * 3;
    const float* pB0 = preds + ((size_t)b * NN + n0 + 512) * 3;
    const float* pB1 = preds + ((size_t)b * NN + n0 + 768) * 3;
    u64 pxA = pk(pA0[0], pA1[0]), pyA = pk(pA0[1], pA1[1]), pzA = pk(pA0[2], pA1[2]);
    u64 pxB = pk(pB0[0], pB1[0]), pyB = pk(pB0[1], pB1[1]), pzB = pk(pB0[2], pB1[2]);
    u64 wpA = pk(efl * g_pn[b*NN+n0],     efl * g_pn[b*NN+n0+256]);
    u64 wpB = pk(efl * g_pn[b*NN+n0+512], efl * g_pn[b*NN+n0+768]);
    const float c2 = -2.0f * efl;
    const u64 c2d = pk(c2, c2);

    u64 rA = 0ull, oA = 0ull, rB = 0ull, oB = 0ull;
#pragma unroll 4
    for (int i = 0; i < CH; i++) {
        float4 L = sl[i];
        float gg = sg[i];
        u64 xd = pk(L.x, L.x), yd = pk(L.y, L.y), zd = pk(L.z, L.z);
        u64 wld = pk(L.w, L.w), gd = pk(gg, gg);
        // pair A
        {
            u64 dot = fma2(zd, pzA, fma2(yd, pyA, mul2(xd, pxA)));
            u64 arg = fma2(dot, c2d, add2(wld, wpA));   // = efl*d
            float a0, a1; upk(arg, a0, a1);
            u64 e = pk(ex2f(a0), ex2f(a1));
            u64 t = mul2(e, gd);
            rA = add2(rA, t);
            oA = fma2(t, arg, oA);      // accumulates efl * sum t*d
        }
        // pair B
        {
            u64 dot = fma2(zd, pzB, fma2(yd, pyB, mul2(xd, pxB)));
            u64 arg = fma2(dot, c2d, add2(wld, wpB));
            float a0, a1; upk(arg, a0, a1);
            u64 e = pk(ex2f(a0), ex2f(a1));
            u64 t = mul2(e, gd);
            rB = add2(rB, t);
            oB = fma2(t, arg, oB);
        }
    }
    float r0, r1, r2, r3, o0, o1, o2, o3;
    upk(rA, r0, r1); upk(rB, r2, r3);
    upk(oA, o0, o1); upk(oB, o2, o3);
    g_Rp[chunk][b*NN+n0      ] = r0;
    g_Rp[chunk][b*NN+n0 + 256] = r1;
    g_Rp[chunk][b*NN+n0 + 512] = r2;
    g_Rp[chunk][b*NN+n0 + 768] = r3;

    float c0 = g_curr[b*NN+n0],       c1 = g_curr[b*NN+n0+256];
    float c2r = g_curr[b*NN+n0+512],  c3 = g_curr[b*NN+n0+768];
    float v = inv_efl * (c0*o0 + c1*o1 + c2r*o2 + c3*o3);
#pragma unroll
    for (int off = 16; off > 0; off >>= 1)
        v += __shfl_down_sync(0xFFFFFFFFu, v, off);
    if ((threadIdx.x & 31) == 0) sred[threadIdx.x >> 5] = v;
    __syncthreads();
    if (threadIdx.x == 0) {
        float s = 0.0f;
#pragma unroll
        for (int w = 0; w < 8; w++) s += sred[w];
        atomicAdd(&g_out, (double)s);
    }
}

__global__ void k_small2() {
    int idx = blockIdx.x * 256 + threadIdx.x;
    if (idx >= BN) return;
    float r = 0.0f;
#pragma unroll
    for (int ch = 0; ch < NCHUNK; ch++) r += g_Rp[ch][idx];
    float c = g_curr[idx];
    g_curr[idx] = fmaxf(c - c * r, 0.0f);
}

// Last step (ef==0): E==1 everywhere. Closed form, O(N) per batch.
// out += G*sum(c*pn) + C*sum(g*lm) - 2*dot(sum(c*p), sum(g*l))
__global__ void k_ef0(const float* __restrict__ preds,
                      const float* __restrict__ labels) {
    const int b = blockIdx.x;
    const int tid = threadIdx.x;
    __shared__ float red[256];

    // phase 1: currency-side sums over n
    float C = 0, CP = 0, CX = 0, CY = 0, CZ = 0;
    for (int n = tid; n < NN; n += 256) {
        float c = g_curr[b * NN + n];
        const float* p = preds + ((size_t)b * NN + n) * 3;
        C += c; CP += c * g_pn[b*NN+n];
        CX += c * p[0]; CY += c * p[1]; CZ += c * p[2];
    }
    auto reduce = [&](float v) -> float {
        red[tid] = v; __syncthreads();
        for (int s = 128; s > 0; s >>= 1) {
            if (tid < s) red[tid] += red[tid + s];
            __syncthreads();
        }
        float r = red[0]; __syncthreads();
        return r;
    };
    float Cs = reduce(C);
    float CPs = reduce(CP);
    float CXs = reduce(CX);
    float CYs = reduce(CY);
    float CZs = reduce(CZ);

    // phase 2: g-side sums over m (se = NN, sec = Cs)
    float G = 0, GL = 0, GX = 0, GY = 0, GZ = 0;
    for (int m = tid; m < NN; m += 256) {
        float cost = g_cost[b * NN + m];
        float s1 = cost * (float)NN;
        float s2 = cost * Cs / (s1 + EPSV);
        float wt = fminf(cost / (s2 + EPSV), 1.0f);
        float g = cost * wt / (s1 + EPSV);
        const float* l = labels + ((size_t)b * NN + m) * 3;
        G += g; GL += g * g_lm[b*NN+m];
        GX += g * l[0]; GY += g * l[1]; GZ += g * l[2];
    }
    float Gs = reduce(G);
    float GLs = reduce(GL);
    float GXs = reduce(GX);
    float GYs = reduce(GY);
    float GZs = reduce(GZ);

    if (tid == 0) {
        double ob = (double)CPs * Gs + (double)Cs * GLs
                  - 2.0 * ((double)CXs * GXs + (double)CYs * GYs + (double)CZs * GZs);
        atomicAdd(&g_out, ob);
    }
}

__global__ void k_write(float* out) {
    out[0] = (float)g_out;
}

extern "C" void kernel_launch(void* const* d_in, const int* in_sizes, int n_in,
                              void* d_out, int out_size) {
    const float* preds = (const float*)d_in[0];
    const float* labels = (const float*)d_in[1];
    float* out = (float*)d_out;

    static const float EF[9] = {
        -16384.0f, -4096.0f, -1024.0f, -256.0f, -64.0f,
        -16.0f, -4.0f, -1.0f, -0.25f
    };
    const float L2E = 1.4426950408889634f;

    k_init<<<BN / 256, 256>>>(preds, labels);

    dim3 grid(NCHUNK, 2, BB);
    for (int s = 0; s < 9; s++) {
        float efl = EF[s] * L2E;
        k_colpass<<<grid, 256>>>(preds, labels, efl);
        k_small1<<<BN / 256, 256>>>();
        k_rowpass<<<grid, 256>>>(preds, labels, efl, 1.0f / efl);
        k_small2<<<BN / 256, 256>>>();
    }
    k_ef0<<<BB, 256>>>(preds, labels);   // ef = 0 step, closed form
    k_write<<<1, 1>>>(out);
}